// round 5
// baseline (speedup 1.0000x reference)
#include <cuda_runtime.h>
#include <math.h>
#include <float.h>
#include <stdint.h>

// ---------------------------------------------------------------------------
// GCN: sparse-extract adjacency -> per layer [3xTF32 mma.sync GEMM + scale,
//      sparse aggregate] -> max/mean pool -> MLP head.
// N <= 10000, DIN = 1024, H = 256, NC = 3
// NOTE: harness PTX target is sm_100 (no 'a'), so only baseline-PTX tensor
// ops (mma.sync) are available — no tcgen05/TMEM.
// ---------------------------------------------------------------------------

#define MAXN   10112
#define MAXNZ  128
#define HDIM   256
#define POOLB  64

__device__ float g_dinv[MAXN];
__device__ int   g_cnt[MAXN];
__device__ int   g_col[MAXN * MAXNZ];
__device__ float g_val[MAXN * MAXNZ];
__device__ float g_y[MAXN * HDIM];      // Y = dinv .* (x @ W)
__device__ float g_x[MAXN * HDIM];      // layer activations
__device__ float g_pmax[POOLB * HDIM];
__device__ float g_psum[POOLB * HDIM];
__device__ float g_wt0[HDIM * 1024];    // W0^T  [256][1024]
__device__ float g_wt1[HDIM * HDIM];    // W1^T  [256][256]
__device__ float g_wt2[HDIM * HDIM];    // W2^T  [256][256]

// ---------------------------------------------------------------------------
__device__ __forceinline__ void split_tf32(float x, uint32_t& h, uint32_t& l) {
    uint32_t hb;
    asm("cvt.rna.tf32.f32 %0, %1;" : "=r"(hb) : "f"(x));
    float lf = x - __uint_as_float(hb);
    uint32_t lb;
    asm("cvt.rna.tf32.f32 %0, %1;" : "=r"(lb) : "f"(lf));
    h = hb; l = lb;
}

__device__ __forceinline__ void mma_tf32(float* d, const uint32_t* a, const uint32_t* b) {
    asm volatile(
        "mma.sync.aligned.m16n8k8.row.col.f32.tf32.tf32.f32 "
        "{%0,%1,%2,%3}, {%4,%5,%6,%7}, {%8,%9}, {%0,%1,%2,%3};"
        : "+f"(d[0]), "+f"(d[1]), "+f"(d[2]), "+f"(d[3])
        : "r"(a[0]), "r"(a[1]), "r"(a[2]), "r"(a[3]), "r"(b[0]), "r"(b[1]));
}

// ---------------------------------------------------------------------------
// Kernel 0: transpose W [K][256] -> WT [256][K]
// ---------------------------------------------------------------------------
__global__ void transpose_kernel(const float* __restrict__ in,
                                 float* __restrict__ out, int K)
{
    __shared__ float t[32][33];
    int kb = blockIdx.x * 32, nb = blockIdx.y * 32;
    int x = threadIdx.x, y = threadIdx.y;   // block (32, 8)
    #pragma unroll
    for (int i = 0; i < 32; i += 8)
        t[y + i][x] = in[(size_t)(kb + y + i) * HDIM + nb + x];
    __syncthreads();
    #pragma unroll
    for (int i = 0; i < 32; i += 8)
        out[(size_t)(nb + y + i) * K + kb + x] = t[x][y + i];
}

// ---------------------------------------------------------------------------
// Kernel 1: row scan -> degree (dinv) + nonzero extraction
// ---------------------------------------------------------------------------
__global__ void extract_kernel(const float* __restrict__ adj, int N)
{
    int row = blockIdx.x;
    int tid = threadIdx.x;
    __shared__ int cnt;
    __shared__ float wsum[8];
    if (tid == 0) cnt = 0;
    __syncthreads();

    const float4* a4 = (const float4*)(adj + (size_t)row * N);
    int n4 = N >> 2;
    float sum = 0.0f;

    for (int i = tid; i < n4; i += 256) {
        float4 v = a4[i];
        sum += (v.x + v.y) + (v.z + v.w);
        int j = i << 2;
        if (v.x != 0.0f && j + 0 != row) { int o = atomicAdd(&cnt, 1); if (o < MAXNZ) { g_col[row*MAXNZ+o] = j+0; g_val[row*MAXNZ+o] = v.x; } }
        if (v.y != 0.0f && j + 1 != row) { int o = atomicAdd(&cnt, 1); if (o < MAXNZ) { g_col[row*MAXNZ+o] = j+1; g_val[row*MAXNZ+o] = v.y; } }
        if (v.z != 0.0f && j + 2 != row) { int o = atomicAdd(&cnt, 1); if (o < MAXNZ) { g_col[row*MAXNZ+o] = j+2; g_val[row*MAXNZ+o] = v.z; } }
        if (v.w != 0.0f && j + 3 != row) { int o = atomicAdd(&cnt, 1); if (o < MAXNZ) { g_col[row*MAXNZ+o] = j+3; g_val[row*MAXNZ+o] = v.w; } }
    }
    for (int j = (n4 << 2) + tid; j < N; j += 256) {
        float v = adj[(size_t)row * N + j];
        sum += v;
        if (v != 0.0f && j != row) { int o = atomicAdd(&cnt, 1); if (o < MAXNZ) { g_col[row*MAXNZ+o] = j; g_val[row*MAXNZ+o] = v; } }
    }

    #pragma unroll
    for (int s = 16; s > 0; s >>= 1) sum += __shfl_xor_sync(0xffffffffu, sum, s);
    if ((tid & 31) == 0) wsum[tid >> 5] = sum;
    __syncthreads();
    if (tid == 0) {
        float t = 0.0f;
        #pragma unroll
        for (int w = 0; w < 8; w++) t += wsum[w];
        g_cnt[row]  = cnt < MAXNZ ? cnt : MAXNZ;
        g_dinv[row] = rsqrtf(t + 1.0f);
    }
}

// ---------------------------------------------------------------------------
// Kernel 2: 3xTF32 mma.sync GEMM: g_y = diag(dinv) * (A @ WT^T)
// A: [M,K] row-major fp32. WT: [256,K] row-major (= B col-major for mma).
// CTA 128x128, BK=16. 8 warps as 2(M)x4(N); warp tile 64x32 = 4x4 m16n8.
// Smem stores hi/lo tf32 split interleaved as float2, k-major, pad 133.
// ---------------------------------------------------------------------------
#define GBK 16

__global__ void __launch_bounds__(256, 2)
gemm_mma_kernel(const float* __restrict__ Aext, const float* __restrict__ WT,
                int M, int K)
{
    __shared__ float2 As[GBK][133];   // [k][m] = {hi, lo}
    __shared__ float2 Bs[GBK][133];   // [k][n] = {hi, lo}

    const float* A = Aext ? Aext : g_x;
    int tid  = threadIdx.x;
    int lane = tid & 31;
    int wid  = tid >> 5;
    int wm   = wid & 1;          // 0..1  -> warp row (64 rows)
    int wn   = wid >> 1;         // 0..3  -> warp col (32 cols)
    int g    = lane >> 2;        // 0..7
    int tg   = lane & 3;         // 0..3
    int bm   = blockIdx.y * 128;
    int bn   = blockIdx.x * 128;

    float acc[4][4][4];
    #pragma unroll
    for (int i = 0; i < 4; i++)
        #pragma unroll
        for (int j = 0; j < 4; j++)
            #pragma unroll
            for (int q = 0; q < 4; q++) acc[i][j][q] = 0.0f;

    // global-load mapping: 512 float4 per tile, 2 per thread
    int e0 = tid, e1 = tid + 256;
    int am0 = e0 >> 2, ak0 = (e0 & 3) << 2;
    int am1 = e1 >> 2, ak1 = (e1 & 3) << 2;
    bool v0 = (bm + am0) < M;
    bool v1 = (bm + am1) < M;
    const float* Ar0 = A + (size_t)(v0 ? bm + am0 : 0) * K;
    const float* Ar1 = A + (size_t)(v1 ? bm + am1 : 0) * K;
    const float* Br0 = WT + (size_t)(bn + am0) * K;
    const float* Br1 = WT + (size_t)(bn + am1) * K;

    int iters = K / GBK;
    for (int it = 0; it < iters; it++) {
        int k0 = it * GBK;
        float4 aV0 = v0 ? *(const float4*)(Ar0 + k0 + ak0) : make_float4(0,0,0,0);
        float4 aV1 = v1 ? *(const float4*)(Ar1 + k0 + ak1) : make_float4(0,0,0,0);
        float4 bV0 = *(const float4*)(Br0 + k0 + ak0);
        float4 bV1 = *(const float4*)(Br1 + k0 + ak1);

        __syncthreads();
        {
            uint32_t h, l;
            float av0[4] = {aV0.x, aV0.y, aV0.z, aV0.w};
            float av1[4] = {aV1.x, aV1.y, aV1.z, aV1.w};
            float bv0[4] = {bV0.x, bV0.y, bV0.z, bV0.w};
            float bv1[4] = {bV1.x, bV1.y, bV1.z, bV1.w};
            #pragma unroll
            for (int j = 0; j < 4; j++) {
                split_tf32(av0[j], h, l);
                As[ak0 + j][am0] = make_float2(__uint_as_float(h), __uint_as_float(l));
                split_tf32(av1[j], h, l);
                As[ak1 + j][am1] = make_float2(__uint_as_float(h), __uint_as_float(l));
                split_tf32(bv0[j], h, l);
                Bs[ak0 + j][am0] = make_float2(__uint_as_float(h), __uint_as_float(l));
                split_tf32(bv1[j], h, l);
                Bs[ak1 + j][am1] = make_float2(__uint_as_float(h), __uint_as_float(l));
            }
        }
        __syncthreads();

        #pragma unroll
        for (int ks = 0; ks < 2; ks++) {
            int kb = ks * 8;
            // B fragments: 4 n-tiles x {b0,b1} hi/lo
            uint32_t bh[4][2], bl[4][2];
            #pragma unroll
            for (int nt = 0; nt < 4; nt++) {
                int n = wn * 32 + nt * 8 + g;
                float2 p0 = Bs[kb + tg][n];
                float2 p1 = Bs[kb + tg + 4][n];
                bh[nt][0] = __float_as_uint(p0.x); bl[nt][0] = __float_as_uint(p0.y);
                bh[nt][1] = __float_as_uint(p1.x); bl[nt][1] = __float_as_uint(p1.y);
            }
            #pragma unroll
            for (int mt = 0; mt < 4; mt++) {
                int m = wm * 64 + mt * 16 + g;
                float2 p0 = As[kb + tg][m];
                float2 p1 = As[kb + tg][m + 8];
                float2 p2 = As[kb + tg + 4][m];
                float2 p3 = As[kb + tg + 4][m + 8];
                uint32_t ah[4] = {__float_as_uint(p0.x), __float_as_uint(p1.x),
                                  __float_as_uint(p2.x), __float_as_uint(p3.x)};
                uint32_t al[4] = {__float_as_uint(p0.y), __float_as_uint(p1.y),
                                  __float_as_uint(p2.y), __float_as_uint(p3.y)};
                #pragma unroll
                for (int nt = 0; nt < 4; nt++) {
                    mma_tf32(acc[mt][nt], ah, bh[nt]);
                    mma_tf32(acc[mt][nt], ah, bl[nt]);
                    mma_tf32(acc[mt][nt], al, bh[nt]);
                }
            }
        }
    }

    // epilogue: scale by dinv, write g_y
    #pragma unroll
    for (int mt = 0; mt < 4; mt++) {
        int r0 = bm + wm * 64 + mt * 16 + g;
        int r1 = r0 + 8;
        float s0 = (r0 < M) ? g_dinv[r0] : 0.0f;
        float s1 = (r1 < M) ? g_dinv[r1] : 0.0f;
        #pragma unroll
        for (int nt = 0; nt < 4; nt++) {
            int col = bn + wn * 32 + nt * 8 + 2 * tg;
            if (r0 < M)
                *(float2*)&g_y[(size_t)r0 * HDIM + col] =
                    make_float2(s0 * acc[mt][nt][0], s0 * acc[mt][nt][1]);
            if (r1 < M)
                *(float2*)&g_y[(size_t)r1 * HDIM + col] =
                    make_float2(s1 * acc[mt][nt][2], s1 * acc[mt][nt][3]);
        }
    }
}

// ---------------------------------------------------------------------------
// Kernel 3: x'[i] = relu( dinv[i] * (Y[i] + sum val*Y[j]) + b )
// ---------------------------------------------------------------------------
__global__ void aggregate_kernel(const float* __restrict__ bias)
{
    int i = blockIdx.x;
    int c = threadIdx.x;            // 0..63
    const float4* y4 = (const float4*)g_y;
    float4 acc = y4[(size_t)i * 64 + c];
    int cnt = g_cnt[i];
    const int*   cols = &g_col[i * MAXNZ];
    const float* vals = &g_val[i * MAXNZ];

    int e = 0;
    for (; e + 2 <= cnt; e += 2) {
        int   c0 = cols[e],  c1 = cols[e+1];
        float v0 = vals[e],  v1 = vals[e+1];
        float4 y0 = y4[(size_t)c0 * 64 + c];
        float4 y1 = y4[(size_t)c1 * 64 + c];
        acc.x += v0*y0.x + v1*y1.x;
        acc.y += v0*y0.y + v1*y1.y;
        acc.z += v0*y0.z + v1*y1.z;
        acc.w += v0*y0.w + v1*y1.w;
    }
    if (e < cnt) {
        int c0 = cols[e]; float v0 = vals[e];
        float4 y0 = y4[(size_t)c0 * 64 + c];
        acc.x += v0*y0.x; acc.y += v0*y0.y; acc.z += v0*y0.z; acc.w += v0*y0.w;
    }

    float s = g_dinv[i];
    float4 b = ((const float4*)bias)[c];
    float4 r;
    r.x = fmaxf(s*acc.x + b.x, 0.0f);
    r.y = fmaxf(s*acc.y + b.y, 0.0f);
    r.z = fmaxf(s*acc.z + b.z, 0.0f);
    r.w = fmaxf(s*acc.w + b.w, 0.0f);
    ((float4*)g_x)[(size_t)i * 64 + c] = r;
}

// ---------------------------------------------------------------------------
// Kernel 4: partial max/sum pool over rows of g_x
// ---------------------------------------------------------------------------
__global__ void pool_partial_kernel(int N)
{
    int c = threadIdx.x;
    float mx = -FLT_MAX;
    float sm = 0.0f;
    for (int r = blockIdx.x; r < N; r += POOLB) {
        float v = g_x[(size_t)r * HDIM + c];
        mx = fmaxf(mx, v);
        sm += v;
    }
    g_pmax[blockIdx.x * HDIM + c] = mx;
    g_psum[blockIdx.x * HDIM + c] = sm;
}

// ---------------------------------------------------------------------------
// Kernel 5: finish pooling + MLP head (single block, 256 threads)
// ---------------------------------------------------------------------------
__global__ void pool_mlp_kernel(const float* __restrict__ C1w, const float* __restrict__ c1b,
                                const float* __restrict__ C2w, const float* __restrict__ c2b,
                                const float* __restrict__ C3w, const float* __restrict__ c3b,
                                float* __restrict__ out, int N)
{
    __shared__ float g[2 * HDIM];
    __shared__ float h1[HDIM];
    __shared__ float h2[HDIM / 2];
    int c = threadIdx.x;

    float mx = -FLT_MAX, sm = 0.0f;
    #pragma unroll
    for (int w = 0; w < POOLB; w++) {
        mx = fmaxf(mx, g_pmax[w * HDIM + c]);
        sm += g_psum[w * HDIM + c];
    }
    g[c] = mx;
    g[HDIM + c] = sm / (float)N;
    __syncthreads();

    float a = c1b[c];
    #pragma unroll 8
    for (int k = 0; k < 2 * HDIM; k++)
        a += g[k] * C1w[(size_t)k * HDIM + c];
    h1[c] = fmaxf(a, 0.0f);
    __syncthreads();

    if (c < HDIM / 2) {
        float a2 = c2b[c];
        #pragma unroll 8
        for (int k = 0; k < HDIM; k++)
            a2 += h1[k] * C2w[(size_t)k * (HDIM / 2) + c];
        h2[c] = fmaxf(a2, 0.0f);
    }
    __syncthreads();

    if (c < 3) {
        float a3 = c3b[c];
        #pragma unroll 8
        for (int k = 0; k < HDIM / 2; k++)
            a3 += h2[k] * C3w[(size_t)k * 3 + c];
        out[c] = a3;
    }
}

// ---------------------------------------------------------------------------
extern "C" void kernel_launch(void* const* d_in, const int* in_sizes, int n_in,
                              void* d_out, int out_size)
{
    const float* features = (const float*)d_in[0];
    const float* adj      = (const float*)d_in[1];
    const float* W0  = (const float*)d_in[2];
    const float* b0  = (const float*)d_in[3];
    const float* W1  = (const float*)d_in[4];
    const float* b1  = (const float*)d_in[5];
    const float* W2  = (const float*)d_in[6];
    const float* b2  = (const float*)d_in[7];
    const float* C1w = (const float*)d_in[8];
    const float* c1b = (const float*)d_in[9];
    const float* C2w = (const float*)d_in[10];
    const float* c2b = (const float*)d_in[11];
    const float* C3w = (const float*)d_in[12];
    const float* c3b = (const float*)d_in[13];
    float* out = (float*)d_out;

    int H   = in_sizes[3];                 // 256
    int DIN = in_sizes[2] / H;             // 1024
    int N   = in_sizes[0] / DIN;           // 10000

    float *wt0, *wt1, *wt2;
    cudaGetSymbolAddress((void**)&wt0, g_wt0);
    cudaGetSymbolAddress((void**)&wt1, g_wt1);
    cudaGetSymbolAddress((void**)&wt2, g_wt2);

    transpose_kernel<<<dim3(DIN / 32, H / 32), dim3(32, 8)>>>(W0, wt0, DIN);
    transpose_kernel<<<dim3(H / 32,  H / 32), dim3(32, 8)>>>(W1, wt1, H);
    transpose_kernel<<<dim3(H / 32,  H / 32), dim3(32, 8)>>>(W2, wt2, H);

    extract_kernel<<<N, 256>>>(adj, N);

    dim3 ggrid(HDIM / 128, (N + 127) / 128);

    gemm_mma_kernel<<<ggrid, 256>>>(features, wt0, N, DIN);
    aggregate_kernel<<<N, 64>>>(b0);
    gemm_mma_kernel<<<ggrid, 256>>>(nullptr, wt1, N, H);
    aggregate_kernel<<<N, 64>>>(b1);
    gemm_mma_kernel<<<ggrid, 256>>>(nullptr, wt2, N, H);
    aggregate_kernel<<<N, 64>>>(b2);

    pool_partial_kernel<<<POOLB, HDIM>>>(N);
    pool_mlp_kernel<<<1, HDIM>>>(C1w, c1b, C2w, c2b, C3w, c3b, out, N);
}

// round 6
// speedup vs baseline: 1.2606x; 1.2606x over previous
#include <cuda_runtime.h>
#include <math.h>
#include <float.h>
#include <stdint.h>

// ---------------------------------------------------------------------------
// GCN: sparse-extract adjacency -> per layer [f32x2 GEMM + scale, sparse
//      aggregate] -> max/mean pool -> MLP head.
// N <= 10000, DIN = 1024, H = 256, NC = 3
// ---------------------------------------------------------------------------

#define MAXN   10112
#define MAXNZ  128
#define HDIM   256
#define POOLB  64

__device__ float g_dinv[MAXN];
__device__ int   g_cnt[MAXN];
__device__ int   g_col[MAXN * MAXNZ];
__device__ float g_val[MAXN * MAXNZ];
__device__ float g_y[MAXN * HDIM];      // Y = dinv .* (x @ W)
__device__ float g_x[MAXN * HDIM];      // layer activations
__device__ float g_pmax[POOLB * HDIM];
__device__ float g_psum[POOLB * HDIM];

typedef unsigned long long ull;

// ---------------------------------------------------------------------------
// Packed f32x2 helpers
// ---------------------------------------------------------------------------
__device__ __forceinline__ void fma2(ull& d, ull a, ull b)
{
    asm("fma.rn.f32x2 %0, %1, %2, %0;" : "+l"(d) : "l"(a), "l"(b));
}
__device__ __forceinline__ ull pack2(float x, float y)
{
    ull r;
    asm("mov.b64 %0, {%1, %2};" : "=l"(r) : "f"(x), "f"(y));
    return r;
}
__device__ __forceinline__ void unpack2(ull v, float& x, float& y)
{
    asm("mov.b64 {%0, %1}, %2;" : "=f"(x), "=f"(y) : "l"(v));
}

// ---------------------------------------------------------------------------
// Kernel 1: row scan -> degree (dinv) + nonzero extraction
// ---------------------------------------------------------------------------
__global__ void extract_kernel(const float* __restrict__ adj, int N)
{
    int row = blockIdx.x;
    int tid = threadIdx.x;
    __shared__ int cnt;
    __shared__ float wsum[8];
    if (tid == 0) cnt = 0;
    __syncthreads();

    const float4* a4 = (const float4*)(adj + (size_t)row * N);
    int n4 = N >> 2;
    float sum = 0.0f;

    for (int i = tid; i < n4; i += 256) {
        float4 v = a4[i];
        sum += (v.x + v.y) + (v.z + v.w);
        int j = i << 2;
        if (v.x != 0.0f && j + 0 != row) { int o = atomicAdd(&cnt, 1); if (o < MAXNZ) { g_col[row*MAXNZ+o] = j+0; g_val[row*MAXNZ+o] = v.x; } }
        if (v.y != 0.0f && j + 1 != row) { int o = atomicAdd(&cnt, 1); if (o < MAXNZ) { g_col[row*MAXNZ+o] = j+1; g_val[row*MAXNZ+o] = v.y; } }
        if (v.z != 0.0f && j + 2 != row) { int o = atomicAdd(&cnt, 1); if (o < MAXNZ) { g_col[row*MAXNZ+o] = j+2; g_val[row*MAXNZ+o] = v.z; } }
        if (v.w != 0.0f && j + 3 != row) { int o = atomicAdd(&cnt, 1); if (o < MAXNZ) { g_col[row*MAXNZ+o] = j+3; g_val[row*MAXNZ+o] = v.w; } }
    }
    for (int j = (n4 << 2) + tid; j < N; j += 256) {
        float v = adj[(size_t)row * N + j];
        sum += v;
        if (v != 0.0f && j != row) { int o = atomicAdd(&cnt, 1); if (o < MAXNZ) { g_col[row*MAXNZ+o] = j; g_val[row*MAXNZ+o] = v; } }
    }

    #pragma unroll
    for (int s = 16; s > 0; s >>= 1) sum += __shfl_xor_sync(0xffffffffu, sum, s);
    if ((tid & 31) == 0) wsum[tid >> 5] = sum;
    __syncthreads();
    if (tid == 0) {
        float t = 0.0f;
        #pragma unroll
        for (int w = 0; w < 8; w++) t += wsum[w];
        g_cnt[row]  = cnt < MAXNZ ? cnt : MAXNZ;
        g_dinv[row] = rsqrtf(t + 1.0f);
    }
}

// ---------------------------------------------------------------------------
// Kernel 2: C = diag(dinv) * (A @ B) -> g_y
// Tile 64(M) x 128(N), BK=16, 256 threads, per-thread 4x8, double-buffered,
// packed f32x2 FMA. B = W row-major [K][256].
// Thread map: tx = tid&15 (cols 4tx..+3 and 64+4tx..+3), ty = tid>>4 (rows 4ty..+3).
// ---------------------------------------------------------------------------
#define ABK 16

__global__ void __launch_bounds__(256, 3)
gemm_f32x2_kernel(const float* __restrict__ Aext, const float* __restrict__ B,
                  int M, int K)
{
    __shared__ float As[2][ABK][68];    // [k][m]
    __shared__ float Bs[2][ABK][132];   // [k][n]

    const float* A = Aext ? Aext : g_x;
    int tid = threadIdx.x;
    int tx = tid & 15;
    int ty = tid >> 4;
    int bm = blockIdx.y * 64;
    int bn = blockIdx.x * 128;

    ull acc[4][4];
    #pragma unroll
    for (int i = 0; i < 4; i++)
        #pragma unroll
        for (int j = 0; j < 4; j++) acc[i][j] = pack2(0.0f, 0.0f);

    // global-load mapping
    int ar  = tid >> 2;            // 0..63  (A row in tile)
    int akq = (tid & 3) << 2;      // 0,4,8,12
    int gm  = bm + ar;
    bool mv = gm < M;
    const float* Arow = A + (size_t)(mv ? gm : 0) * K;

    int bk0 = tid >> 5;            // 0..7   (B: 2 f4/thread: rows bk0, bk0+8)
    int bc  = (tid & 31) << 2;     // 0..124

    // prologue: fill buffer 0
    {
        float4 aV = mv ? *(const float4*)&Arow[akq] : make_float4(0,0,0,0);
        As[0][akq+0][ar] = aV.x; As[0][akq+1][ar] = aV.y;
        As[0][akq+2][ar] = aV.z; As[0][akq+3][ar] = aV.w;
        float4 b0 = *(const float4*)&B[(size_t)bk0 * HDIM + bn + bc];
        float4 b1 = *(const float4*)&B[(size_t)(bk0 + 8) * HDIM + bn + bc];
        *(float4*)&Bs[0][bk0][bc]     = b0;
        *(float4*)&Bs[0][bk0 + 8][bc] = b1;
    }
    __syncthreads();

    int buf = 0;
    for (int k0 = ABK; k0 < K; k0 += ABK) {
        float4 aN = mv ? *(const float4*)&Arow[k0 + akq] : make_float4(0,0,0,0);
        float4 bN0 = *(const float4*)&B[(size_t)(k0 + bk0) * HDIM + bn + bc];
        float4 bN1 = *(const float4*)&B[(size_t)(k0 + bk0 + 8) * HDIM + bn + bc];

        #pragma unroll
        for (int k = 0; k < ABK; k++) {
            float4 av = *(const float4*)&As[buf][k][ty * 4];
            float4 b0 = *(const float4*)&Bs[buf][k][tx * 4];
            float4 b1 = *(const float4*)&Bs[buf][k][64 + tx * 4];
            ull bp0 = pack2(b0.x, b0.y);
            ull bp1 = pack2(b0.z, b0.w);
            ull bp2 = pack2(b1.x, b1.y);
            ull bp3 = pack2(b1.z, b1.w);
            float arr[4] = {av.x, av.y, av.z, av.w};
            #pragma unroll
            for (int i = 0; i < 4; i++) {
                ull ap = pack2(arr[i], arr[i]);
                fma2(acc[i][0], ap, bp0);
                fma2(acc[i][1], ap, bp1);
                fma2(acc[i][2], ap, bp2);
                fma2(acc[i][3], ap, bp3);
            }
        }

        As[buf^1][akq+0][ar] = aN.x; As[buf^1][akq+1][ar] = aN.y;
        As[buf^1][akq+2][ar] = aN.z; As[buf^1][akq+3][ar] = aN.w;
        *(float4*)&Bs[buf^1][bk0][bc]     = bN0;
        *(float4*)&Bs[buf^1][bk0 + 8][bc] = bN1;
        __syncthreads();
        buf ^= 1;
    }

    // final tile
    #pragma unroll
    for (int k = 0; k < ABK; k++) {
        float4 av = *(const float4*)&As[buf][k][ty * 4];
        float4 b0 = *(const float4*)&Bs[buf][k][tx * 4];
        float4 b1 = *(const float4*)&Bs[buf][k][64 + tx * 4];
        ull bp0 = pack2(b0.x, b0.y);
        ull bp1 = pack2(b0.z, b0.w);
        ull bp2 = pack2(b1.x, b1.y);
        ull bp3 = pack2(b1.z, b1.w);
        float arr[4] = {av.x, av.y, av.z, av.w};
        #pragma unroll
        for (int i = 0; i < 4; i++) {
            ull ap = pack2(arr[i], arr[i]);
            fma2(acc[i][0], ap, bp0);
            fma2(acc[i][1], ap, bp1);
            fma2(acc[i][2], ap, bp2);
            fma2(acc[i][3], ap, bp3);
        }
    }

    // epilogue: scale rows by dinv, write g_y
    #pragma unroll
    for (int i = 0; i < 4; i++) {
        int m = bm + ty * 4 + i;
        if (m >= M) continue;
        float s = g_dinv[m];
        float o0, o1, o2, o3, o4, o5, o6, o7;
        unpack2(acc[i][0], o0, o1);
        unpack2(acc[i][1], o2, o3);
        unpack2(acc[i][2], o4, o5);
        unpack2(acc[i][3], o6, o7);
        float* dst = &g_y[(size_t)m * HDIM + bn];
        *(float4*)(dst + tx * 4)      = make_float4(s*o0, s*o1, s*o2, s*o3);
        *(float4*)(dst + 64 + tx * 4) = make_float4(s*o4, s*o5, s*o6, s*o7);
    }
}

// ---------------------------------------------------------------------------
// Kernel 3: x'[i] = relu( dinv[i] * (Y[i] + sum val*Y[j]) + b )
// ---------------------------------------------------------------------------
__global__ void aggregate_kernel(const float* __restrict__ bias)
{
    int i = blockIdx.x;
    int c = threadIdx.x;            // 0..63
    const float4* y4 = (const float4*)g_y;
    float4 acc = y4[(size_t)i * 64 + c];
    int cnt = g_cnt[i];
    const int*   cols = &g_col[i * MAXNZ];
    const float* vals = &g_val[i * MAXNZ];

    int e = 0;
    for (; e + 2 <= cnt; e += 2) {
        int   c0 = cols[e],  c1 = cols[e+1];
        float v0 = vals[e],  v1 = vals[e+1];
        float4 y0 = y4[(size_t)c0 * 64 + c];
        float4 y1 = y4[(size_t)c1 * 64 + c];
        acc.x += v0*y0.x + v1*y1.x;
        acc.y += v0*y0.y + v1*y1.y;
        acc.z += v0*y0.z + v1*y1.z;
        acc.w += v0*y0.w + v1*y1.w;
    }
    if (e < cnt) {
        int c0 = cols[e]; float v0 = vals[e];
        float4 y0 = y4[(size_t)c0 * 64 + c];
        acc.x += v0*y0.x; acc.y += v0*y0.y; acc.z += v0*y0.z; acc.w += v0*y0.w;
    }

    float s = g_dinv[i];
    float4 b = ((const float4*)bias)[c];
    float4 r;
    r.x = fmaxf(s*acc.x + b.x, 0.0f);
    r.y = fmaxf(s*acc.y + b.y, 0.0f);
    r.z = fmaxf(s*acc.z + b.z, 0.0f);
    r.w = fmaxf(s*acc.w + b.w, 0.0f);
    ((float4*)g_x)[(size_t)i * 64 + c] = r;
}

// ---------------------------------------------------------------------------
// Kernel 4: partial max/sum pool over rows of g_x
// ---------------------------------------------------------------------------
__global__ void pool_partial_kernel(int N)
{
    int c = threadIdx.x;
    float mx = -FLT_MAX;
    float sm = 0.0f;
    for (int r = blockIdx.x; r < N; r += POOLB) {
        float v = g_x[(size_t)r * HDIM + c];
        mx = fmaxf(mx, v);
        sm += v;
    }
    g_pmax[blockIdx.x * HDIM + c] = mx;
    g_psum[blockIdx.x * HDIM + c] = sm;
}

// ---------------------------------------------------------------------------
// Kernel 5: finish pooling + MLP head (single block, 256 threads)
// ---------------------------------------------------------------------------
__global__ void pool_mlp_kernel(const float* __restrict__ C1w, const float* __restrict__ c1b,
                                const float* __restrict__ C2w, const float* __restrict__ c2b,
                                const float* __restrict__ C3w, const float* __restrict__ c3b,
                                float* __restrict__ out, int N)
{
    __shared__ float g[2 * HDIM];
    __shared__ float h1[HDIM];
    __shared__ float h2[HDIM / 2];
    int c = threadIdx.x;

    float mx = -FLT_MAX, sm = 0.0f;
    #pragma unroll
    for (int w = 0; w < POOLB; w++) {
        mx = fmaxf(mx, g_pmax[w * HDIM + c]);
        sm += g_psum[w * HDIM + c];
    }
    g[c] = mx;
    g[HDIM + c] = sm / (float)N;
    __syncthreads();

    float a = c1b[c];
    #pragma unroll 8
    for (int k = 0; k < 2 * HDIM; k++)
        a += g[k] * C1w[(size_t)k * HDIM + c];
    h1[c] = fmaxf(a, 0.0f);
    __syncthreads();

    if (c < HDIM / 2) {
        float a2 = c2b[c];
        #pragma unroll 8
        for (int k = 0; k < HDIM; k++)
            a2 += h1[k] * C2w[(size_t)k * (HDIM / 2) + c];
        h2[c] = fmaxf(a2, 0.0f);
    }
    __syncthreads();

    if (c < 3) {
        float a3 = c3b[c];
        #pragma unroll 8
        for (int k = 0; k < HDIM / 2; k++)
            a3 += h2[k] * C3w[(size_t)k * 3 + c];
        out[c] = a3;
    }
}

// ---------------------------------------------------------------------------
extern "C" void kernel_launch(void* const* d_in, const int* in_sizes, int n_in,
                              void* d_out, int out_size)
{
    const float* features = (const float*)d_in[0];
    const float* adj      = (const float*)d_in[1];
    const float* W0  = (const float*)d_in[2];
    const float* b0  = (const float*)d_in[3];
    const float* W1  = (const float*)d_in[4];
    const float* b1  = (const float*)d_in[5];
    const float* W2  = (const float*)d_in[6];
    const float* b2  = (const float*)d_in[7];
    const float* C1w = (const float*)d_in[8];
    const float* c1b = (const float*)d_in[9];
    const float* C2w = (const float*)d_in[10];
    const float* c2b = (const float*)d_in[11];
    const float* C3w = (const float*)d_in[12];
    const float* c3b = (const float*)d_in[13];
    float* out = (float*)d_out;

    int H   = in_sizes[3];                 // 256
    int DIN = in_sizes[2] / H;             // 1024
    int N   = in_sizes[0] / DIN;           // 10000

    extract_kernel<<<N, 256>>>(adj, N);

    dim3 ggrid(HDIM / 128, (N + 63) / 64);

    gemm_f32x2_kernel<<<ggrid, 256>>>(features, W0, N, DIN);
    aggregate_kernel<<<N, 64>>>(b0);
    gemm_f32x2_kernel<<<ggrid, 256>>>(nullptr, W1, N, H);
    aggregate_kernel<<<N, 64>>>(b1);
    gemm_f32x2_kernel<<<ggrid, 256>>>(nullptr, W2, N, H);
    aggregate_kernel<<<N, 64>>>(b2);

    pool_partial_kernel<<<POOLB, HDIM>>>(N);
    pool_mlp_kernel<<<1, HDIM>>>(C1w, c1b, C2w, c2b, C3w, c3b, out, N);
}

// round 7
// speedup vs baseline: 1.3525x; 1.0729x over previous
#include <cuda_runtime.h>
#include <math.h>
#include <float.h>
#include <stdint.h>

// ---------------------------------------------------------------------------
// GCN: sparse-extract adjacency (overlapped with L0 GEMM) -> per layer
//      [f32x2 GEMM, sparse aggregate w/ dinv] -> max/mean pool -> MLP head.
// N <= 10000, DIN = 1024, H = 256, NC = 3
// ---------------------------------------------------------------------------

#define MAXN   10112
#define MAXNZ  128
#define HDIM   256
#define POOLB  64

__device__ float g_dinv[MAXN];
__device__ int   g_cnt[MAXN];
__device__ int   g_col[MAXN * MAXNZ];
__device__ float g_val[MAXN * MAXNZ];
__device__ float g_y[MAXN * HDIM];      // Y = x @ W  (unscaled)
__device__ float g_x[MAXN * HDIM];      // layer activations
__device__ float g_pmax[POOLB * HDIM];
__device__ float g_psum[POOLB * HDIM];

typedef unsigned long long ull;

__device__ __forceinline__ void fma2(ull& d, ull a, ull b)
{
    asm("fma.rn.f32x2 %0, %1, %2, %0;" : "+l"(d) : "l"(a), "l"(b));
}
__device__ __forceinline__ ull pack2(float x, float y)
{
    ull r;
    asm("mov.b64 %0, {%1, %2};" : "=l"(r) : "f"(x), "f"(y));
    return r;
}
__device__ __forceinline__ void unpack2(ull v, float& x, float& y)
{
    asm("mov.b64 {%0, %1}, %2;" : "=f"(x), "=f"(y) : "l"(v));
}

// ---------------------------------------------------------------------------
// Kernel 1: row scan -> degree (dinv) + nonzero extraction
// ---------------------------------------------------------------------------
__global__ void extract_kernel(const float* __restrict__ adj, int N)
{
    int row = blockIdx.x;
    int tid = threadIdx.x;
    __shared__ int cnt;
    __shared__ float wsum[8];
    if (tid == 0) cnt = 0;
    __syncthreads();

    const float4* a4 = (const float4*)(adj + (size_t)row * N);
    int n4 = N >> 2;
    float sum = 0.0f;

    for (int i = tid; i < n4; i += 256) {
        float4 v = a4[i];
        sum += (v.x + v.y) + (v.z + v.w);
        int j = i << 2;
        if (v.x != 0.0f && j + 0 != row) { int o = atomicAdd(&cnt, 1); if (o < MAXNZ) { g_col[row*MAXNZ+o] = j+0; g_val[row*MAXNZ+o] = v.x; } }
        if (v.y != 0.0f && j + 1 != row) { int o = atomicAdd(&cnt, 1); if (o < MAXNZ) { g_col[row*MAXNZ+o] = j+1; g_val[row*MAXNZ+o] = v.y; } }
        if (v.z != 0.0f && j + 2 != row) { int o = atomicAdd(&cnt, 1); if (o < MAXNZ) { g_col[row*MAXNZ+o] = j+2; g_val[row*MAXNZ+o] = v.z; } }
        if (v.w != 0.0f && j + 3 != row) { int o = atomicAdd(&cnt, 1); if (o < MAXNZ) { g_col[row*MAXNZ+o] = j+3; g_val[row*MAXNZ+o] = v.w; } }
    }
    for (int j = (n4 << 2) + tid; j < N; j += 256) {
        float v = adj[(size_t)row * N + j];
        sum += v;
        if (v != 0.0f && j != row) { int o = atomicAdd(&cnt, 1); if (o < MAXNZ) { g_col[row*MAXNZ+o] = j; g_val[row*MAXNZ+o] = v; } }
    }

    #pragma unroll
    for (int s = 16; s > 0; s >>= 1) sum += __shfl_xor_sync(0xffffffffu, sum, s);
    if ((tid & 31) == 0) wsum[tid >> 5] = sum;
    __syncthreads();
    if (tid == 0) {
        float t = 0.0f;
        #pragma unroll
        for (int w = 0; w < 8; w++) t += wsum[w];
        g_cnt[row]  = cnt < MAXNZ ? cnt : MAXNZ;
        g_dinv[row] = rsqrtf(t + 1.0f);
    }
}

// ---------------------------------------------------------------------------
// Kernel 2: C = A @ B -> g_y   (no scaling; dinv applied in aggregate)
// Tile 64(M) x 128(N), BK=16, 128 threads, per-thread 8x8, double-buffered,
// packed f32x2 FMA. B = W row-major [K][256].
// ---------------------------------------------------------------------------
#define ABK 16

__global__ void __launch_bounds__(128, 3)
gemm_f32x2_kernel(const float* __restrict__ Aext, const float* __restrict__ B,
                  int M, int K)
{
    __shared__ float As[2][ABK][68];    // [k][m]
    __shared__ float Bs[2][ABK][132];   // [k][n]

    const float* A = Aext ? Aext : g_x;
    int tid = threadIdx.x;
    int tx = tid & 15;      // 0..15 -> cols 4tx..+3 and 64+4tx..+3
    int ty = tid >> 4;      // 0..7  -> rows 8ty..+7
    int bm = blockIdx.y * 64;
    int bn = blockIdx.x * 128;

    ull acc[8][4];
    #pragma unroll
    for (int i = 0; i < 8; i++)
        #pragma unroll
        for (int j = 0; j < 4; j++) acc[i][j] = pack2(0.0f, 0.0f);

    // global-load mapping
    int ar = tid >> 1;             // 0..63
    int ak = (tid & 1) << 3;       // 0 or 8: two float4 at ak, ak+4
    int gm = bm + ar;
    bool mv = gm < M;
    const float* Arow = A + (size_t)(mv ? gm : 0) * K;

    int bk = tid >> 5;             // 0..3: rows bk, bk+4, bk+8, bk+12
    int bc = (tid & 31) << 2;      // 0..124

    // prologue: fill buffer 0
    {
        float4 a0 = mv ? *(const float4*)&Arow[ak]     : make_float4(0,0,0,0);
        float4 a1 = mv ? *(const float4*)&Arow[ak + 4] : make_float4(0,0,0,0);
        As[0][ak+0][ar] = a0.x; As[0][ak+1][ar] = a0.y;
        As[0][ak+2][ar] = a0.z; As[0][ak+3][ar] = a0.w;
        As[0][ak+4][ar] = a1.x; As[0][ak+5][ar] = a1.y;
        As[0][ak+6][ar] = a1.z; As[0][ak+7][ar] = a1.w;
        #pragma unroll
        for (int t = 0; t < 4; t++)
            *(float4*)&Bs[0][bk + 4*t][bc] =
                *(const float4*)&B[(size_t)(bk + 4*t) * HDIM + bn + bc];
    }
    __syncthreads();

    int buf = 0;
    for (int k0 = ABK; k0 < K; k0 += ABK) {
        float4 aN0 = mv ? *(const float4*)&Arow[k0 + ak]     : make_float4(0,0,0,0);
        float4 aN1 = mv ? *(const float4*)&Arow[k0 + ak + 4] : make_float4(0,0,0,0);
        float4 bN[4];
        #pragma unroll
        for (int t = 0; t < 4; t++)
            bN[t] = *(const float4*)&B[(size_t)(k0 + bk + 4*t) * HDIM + bn + bc];

        #pragma unroll
        for (int k = 0; k < ABK; k++) {
            float4 av0 = *(const float4*)&As[buf][k][ty * 8];
            float4 av1 = *(const float4*)&As[buf][k][ty * 8 + 4];
            float4 b0  = *(const float4*)&Bs[buf][k][tx * 4];
            float4 b1  = *(const float4*)&Bs[buf][k][64 + tx * 4];
            ull bp0 = pack2(b0.x, b0.y);
            ull bp1 = pack2(b0.z, b0.w);
            ull bp2 = pack2(b1.x, b1.y);
            ull bp3 = pack2(b1.z, b1.w);
            float arr[8] = {av0.x, av0.y, av0.z, av0.w, av1.x, av1.y, av1.z, av1.w};
            #pragma unroll
            for (int i = 0; i < 8; i++) {
                ull ap = pack2(arr[i], arr[i]);
                fma2(acc[i][0], ap, bp0);
                fma2(acc[i][1], ap, bp1);
                fma2(acc[i][2], ap, bp2);
                fma2(acc[i][3], ap, bp3);
            }
        }

        As[buf^1][ak+0][ar] = aN0.x; As[buf^1][ak+1][ar] = aN0.y;
        As[buf^1][ak+2][ar] = aN0.z; As[buf^1][ak+3][ar] = aN0.w;
        As[buf^1][ak+4][ar] = aN1.x; As[buf^1][ak+5][ar] = aN1.y;
        As[buf^1][ak+6][ar] = aN1.z; As[buf^1][ak+7][ar] = aN1.w;
        #pragma unroll
        for (int t = 0; t < 4; t++)
            *(float4*)&Bs[buf^1][bk + 4*t][bc] = bN[t];
        __syncthreads();
        buf ^= 1;
    }

    // final tile
    #pragma unroll
    for (int k = 0; k < ABK; k++) {
        float4 av0 = *(const float4*)&As[buf][k][ty * 8];
        float4 av1 = *(const float4*)&As[buf][k][ty * 8 + 4];
        float4 b0  = *(const float4*)&Bs[buf][k][tx * 4];
        float4 b1  = *(const float4*)&Bs[buf][k][64 + tx * 4];
        ull bp0 = pack2(b0.x, b0.y);
        ull bp1 = pack2(b0.z, b0.w);
        ull bp2 = pack2(b1.x, b1.y);
        ull bp3 = pack2(b1.z, b1.w);
        float arr[8] = {av0.x, av0.y, av0.z, av0.w, av1.x, av1.y, av1.z, av1.w};
        #pragma unroll
        for (int i = 0; i < 8; i++) {
            ull ap = pack2(arr[i], arr[i]);
            fma2(acc[i][0], ap, bp0);
            fma2(acc[i][1], ap, bp1);
            fma2(acc[i][2], ap, bp2);
            fma2(acc[i][3], ap, bp3);
        }
    }

    // epilogue: write g_y (unscaled)
    #pragma unroll
    for (int i = 0; i < 8; i++) {
        int m = bm + ty * 8 + i;
        if (m >= M) continue;
        float o0, o1, o2, o3, o4, o5, o6, o7;
        unpack2(acc[i][0], o0, o1);
        unpack2(acc[i][1], o2, o3);
        unpack2(acc[i][2], o4, o5);
        unpack2(acc[i][3], o6, o7);
        float* dst = &g_y[(size_t)m * HDIM + bn];
        *(float4*)(dst + tx * 4)      = make_float4(o0, o1, o2, o3);
        *(float4*)(dst + 64 + tx * 4) = make_float4(o4, o5, o6, o7);
    }
}

// ---------------------------------------------------------------------------
// Kernel 3: x'[i] = relu( dinv_i*( dinv_i*Y_i + sum val*dinv_j*Y_j ) + b )
// ---------------------------------------------------------------------------
__global__ void aggregate_kernel(const float* __restrict__ bias)
{
    int i = blockIdx.x;
    int c = threadIdx.x;            // 0..63
    const float4* y4 = (const float4*)g_y;
    float si = g_dinv[i];
    float4 self = y4[(size_t)i * 64 + c];
    float4 acc;
    acc.x = si * self.x; acc.y = si * self.y;
    acc.z = si * self.z; acc.w = si * self.w;

    int cnt = g_cnt[i];
    const int*   cols = &g_col[i * MAXNZ];
    const float* vals = &g_val[i * MAXNZ];

    int e = 0;
    for (; e + 2 <= cnt; e += 2) {
        int   c0 = cols[e],  c1 = cols[e+1];
        float v0 = vals[e] * g_dinv[c0];
        float v1 = vals[e+1] * g_dinv[c1];
        float4 y0 = y4[(size_t)c0 * 64 + c];
        float4 y1 = y4[(size_t)c1 * 64 + c];
        acc.x += v0*y0.x + v1*y1.x;
        acc.y += v0*y0.y + v1*y1.y;
        acc.z += v0*y0.z + v1*y1.z;
        acc.w += v0*y0.w + v1*y1.w;
    }
    if (e < cnt) {
        int c0 = cols[e];
        float v0 = vals[e] * g_dinv[c0];
        float4 y0 = y4[(size_t)c0 * 64 + c];
        acc.x += v0*y0.x; acc.y += v0*y0.y; acc.z += v0*y0.z; acc.w += v0*y0.w;
    }

    float4 b = ((const float4*)bias)[c];
    float4 r;
    r.x = fmaxf(si*acc.x + b.x, 0.0f);
    r.y = fmaxf(si*acc.y + b.y, 0.0f);
    r.z = fmaxf(si*acc.z + b.z, 0.0f);
    r.w = fmaxf(si*acc.w + b.w, 0.0f);
    ((float4*)g_x)[(size_t)i * 64 + c] = r;
}

// ---------------------------------------------------------------------------
// Kernel 4: partial max/sum pool over rows of g_x
// ---------------------------------------------------------------------------
__global__ void pool_partial_kernel(int N)
{
    int c = threadIdx.x;
    float mx = -FLT_MAX;
    float sm = 0.0f;
    for (int r = blockIdx.x; r < N; r += POOLB) {
        float v = g_x[(size_t)r * HDIM + c];
        mx = fmaxf(mx, v);
        sm += v;
    }
    g_pmax[blockIdx.x * HDIM + c] = mx;
    g_psum[blockIdx.x * HDIM + c] = sm;
}

// ---------------------------------------------------------------------------
// Kernel 5: finish pooling + MLP head (single block, 256 threads)
// ---------------------------------------------------------------------------
__global__ void pool_mlp_kernel(const float* __restrict__ C1w, const float* __restrict__ c1b,
                                const float* __restrict__ C2w, const float* __restrict__ c2b,
                                const float* __restrict__ C3w, const float* __restrict__ c3b,
                                float* __restrict__ out, int N)
{
    __shared__ float g[2 * HDIM];
    __shared__ float h1[HDIM];
    __shared__ float h2[HDIM / 2];
    int c = threadIdx.x;

    float mx = -FLT_MAX, sm = 0.0f;
    #pragma unroll
    for (int w = 0; w < POOLB; w++) {
        mx = fmaxf(mx, g_pmax[w * HDIM + c]);
        sm += g_psum[w * HDIM + c];
    }
    g[c] = mx;
    g[HDIM + c] = sm / (float)N;
    __syncthreads();

    float a = c1b[c];
    #pragma unroll 8
    for (int k = 0; k < 2 * HDIM; k++)
        a += g[k] * C1w[(size_t)k * HDIM + c];
    h1[c] = fmaxf(a, 0.0f);
    __syncthreads();

    if (c < HDIM / 2) {
        float a2 = c2b[c];
        #pragma unroll 8
        for (int k = 0; k < HDIM; k++)
            a2 += h1[k] * C2w[(size_t)k * (HDIM / 2) + c];
        h2[c] = fmaxf(a2, 0.0f);
    }
    __syncthreads();

    if (c < 3) {
        float a3 = c3b[c];
        #pragma unroll 8
        for (int k = 0; k < HDIM / 2; k++)
            a3 += h2[k] * C3w[(size_t)k * 3 + c];
        out[c] = a3;
    }
}

// ---------------------------------------------------------------------------
extern "C" void kernel_launch(void* const* d_in, const int* in_sizes, int n_in,
                              void* d_out, int out_size)
{
    const float* features = (const float*)d_in[0];
    const float* adj      = (const float*)d_in[1];
    const float* W0  = (const float*)d_in[2];
    const float* b0  = (const float*)d_in[3];
    const float* W1  = (const float*)d_in[4];
    const float* b1  = (const float*)d_in[5];
    const float* W2  = (const float*)d_in[6];
    const float* b2  = (const float*)d_in[7];
    const float* C1w = (const float*)d_in[8];
    const float* c1b = (const float*)d_in[9];
    const float* C2w = (const float*)d_in[10];
    const float* c2b = (const float*)d_in[11];
    const float* C3w = (const float*)d_in[12];
    const float* c3b = (const float*)d_in[13];
    float* out = (float*)d_out;

    int H   = in_sizes[3];                 // 256
    int DIN = in_sizes[2] / H;             // 1024
    int N   = in_sizes[0] / DIN;           // 10000

    // side stream + events for extract/GEMM overlap (host resources only)
    static cudaStream_t s2 = nullptr;
    static cudaEvent_t  ef = nullptr, ej = nullptr;
    if (s2 == nullptr) {
        cudaStreamCreateWithFlags(&s2, cudaStreamNonBlocking);
        cudaEventCreateWithFlags(&ef, cudaEventDisableTiming);
        cudaEventCreateWithFlags(&ej, cudaEventDisableTiming);
    }

    dim3 ggrid(HDIM / 128, (N + 63) / 64);

    // fork: extract on side stream, L0 GEMM on main stream (independent)
    cudaEventRecord(ef, 0);
    cudaStreamWaitEvent(s2, ef, 0);
    extract_kernel<<<N, 256, 0, s2>>>(adj, N);
    cudaEventRecord(ej, s2);

    gemm_f32x2_kernel<<<ggrid, 128>>>(features, W0, N, DIN);

    // join: aggregate needs both GEMM output and extract output
    cudaStreamWaitEvent(0, ej, 0);
    aggregate_kernel<<<N, 64>>>(b0);

    gemm_f32x2_kernel<<<ggrid, 128>>>(nullptr, W1, N, H);
    aggregate_kernel<<<N, 64>>>(b1);
    gemm_f32x2_kernel<<<ggrid, 128>>>(nullptr, W2, N, H);
    aggregate_kernel<<<N, 64>>>(b2);

    pool_partial_kernel<<<POOLB, HDIM>>>(N);
    pool_mlp_kernel<<<1, HDIM>>>(C1w, c1b, C2w, c2b, C3w, c3b, out, N);
}